// round 3
// baseline (speedup 1.0000x reference)
#include <cuda_runtime.h>

#define Bb 2
#define Nn 2000
#define Ff 64
#define Dd 128
#define NHEADS 4
#define DH 32
#define HN 3
#define DEEP 384
#define SLOPE 0.1f
#define NEG_INF -1e30f
#define TJ 64
#define TI 16

__device__ float g_hbuf[Bb*Nn*Dd];
__device__ float g_ssrc[Bb*NHEADS*Nn];
__device__ float g_sdst[Bb*NHEADS*Nn];
__device__ float g_abar[HN*Bb*Ff];

__device__ __forceinline__ float lrelu(float x){ return x > 0.f ? x : SLOPE*x; }

// ---------------- BN + encoder MLP: features -> C ----------------
__global__ void encoder_kernel(const float* __restrict__ feats,
    const float* __restrict__ gamma, const float* __restrict__ beta,
    const float* __restrict__ mean, const float* __restrict__ var,
    const float* __restrict__ W1, const float* __restrict__ b1,
    const float* __restrict__ W2, const float* __restrict__ b2,
    float* __restrict__ C)
{
    __shared__ float xn[16][Ff];
    __shared__ float hid[16][Dd];
    int tid = threadIdx.x;
    int row0 = blockIdx.x * 16;
    for (int idx = tid; idx < 16*Ff; idx += 128) {
        int r = idx >> 6, f = idx & 63;
        float v = feats[(row0+r)*Ff + f];
        xn[r][f] = (v - mean[f]) * rsqrtf(var[f] + 1e-5f) * gamma[f] + beta[f];
    }
    __syncthreads();
    float acc[16];
    float bb = b1[tid];
    #pragma unroll
    for (int r=0;r<16;r++) acc[r] = bb;
    for (int f=0; f<Ff; f++){
        float w = W1[f*Dd + tid];
        #pragma unroll
        for (int r=0;r<16;r++) acc[r] += xn[r][f]*w;
    }
    #pragma unroll
    for (int r=0;r<16;r++) hid[r][tid] = fmaxf(acc[r], 0.f);
    __syncthreads();
    bb = b2[tid];
    #pragma unroll
    for (int r=0;r<16;r++) acc[r] = bb;
    for (int k=0;k<Dd;k++){
        float w = W2[k*Dd + tid];
        #pragma unroll
        for (int r=0;r<16;r++) acc[r] += hid[r][k]*w;
    }
    #pragma unroll
    for (int r=0;r<16;r++) C[(size_t)(row0+r)*Dd + tid] = acc[r];
}

// ---------------- GAT projection: h = X@W, s_src, s_dst ----------------
__global__ void gat_proj_kernel(const float* __restrict__ X,
    const float* __restrict__ W, const float* __restrict__ a_src,
    const float* __restrict__ a_dst)
{
    __shared__ float xs[16][Dd];
    int tid = threadIdx.x;
    int row0 = blockIdx.x * 16;
    for (int idx = tid; idx < 16*Dd; idx += 128){
        int r = idx >> 7, c = idx & 127;
        xs[r][c] = X[(size_t)(row0+r)*Dd + c];
    }
    __syncthreads();
    float acc[16];
    #pragma unroll
    for (int r=0;r<16;r++) acc[r]=0.f;
    for (int k=0;k<Dd;k++){
        float w = W[k*Dd + tid];
        #pragma unroll
        for (int r=0;r<16;r++) acc[r] += xs[r][k]*w;
    }
    int head = tid >> 5, lane = tid & 31;
    float av = a_src[head*DH + lane];
    float bv = a_dst[head*DH + lane];
    #pragma unroll
    for (int r=0;r<16;r++){
        int g = row0 + r;
        g_hbuf[(size_t)g*Dd + tid] = acc[r];
        float p = acc[r]*av, q = acc[r]*bv;
        #pragma unroll
        for (int off=16; off; off>>=1){
            p += __shfl_xor_sync(0xffffffffu, p, off);
            q += __shfl_xor_sync(0xffffffffu, q, off);
        }
        if (lane == 0){
            int b = g / Nn, n = g % Nn;
            g_ssrc[(b*NHEADS+head)*Nn + n] = p;
            g_sdst[(b*NHEADS+head)*Nn + n] = q;
        }
    }
}

// ---------------- GAT attention: online softmax + aggregation ----------------
// Mask is read as 32-bit words (covers int32 OR float32 bool storage: !=0 test
// is identical for both). Block: 256 threads (8 warps), TI=16 query rows.
__global__ void gat_attn_kernel(const int* __restrict__ mask,
    const float* __restrict__ Cin, float* __restrict__ Hout, float* __restrict__ Cbar)
{
    __shared__ float h_tile[TJ][132];
    __shared__ float t_tile[NHEADS][TJ];
    __shared__ unsigned char m_tile[TI][TJ];
    __shared__ float wb[8][2][TJ];

    int tid = threadIdx.x;
    int w = tid >> 5, lane = tid & 31;
    int b  = blockIdx.x / (Nn/TI);
    int i0 = (blockIdx.x % (Nn/TI)) * TI;

    float accv[8], mv[8], lv[8], sv[8];
    #pragma unroll
    for (int s=0;s<8;s++){
        accv[s]=0.f; mv[s]=NEG_INF; lv[s]=0.f;
        int rh = w*8+s;
        int i_l = rh>>2, head = rh&3;
        sv[s] = g_ssrc[(b*NHEADS+head)*Nn + i0 + i_l];
    }

    const float* hb = g_hbuf + (size_t)b*Nn*Dd;
    const int* mrow = mask + (size_t)b*Nn*Nn;

    for (int j0 = 0; j0 < Nn; j0 += TJ){
        __syncthreads();
        // h tile (zero-fill past N)
        for (int idx = tid; idx < TJ*(Dd/4); idx += 256){
            int jj = idx >> 5;
            int c4 = idx & 31;
            float4 v = make_float4(0.f,0.f,0.f,0.f);
            if (j0+jj < Nn) v = *(const float4*)(hb + (size_t)(j0+jj)*Dd + c4*4);
            *(float4*)&h_tile[jj][c4*4] = v;
        }
        // s_dst tile
        for (int idx = tid; idx < NHEADS*TJ; idx += 256){
            int h = idx / TJ, jj = idx % TJ;
            t_tile[h][jj] = (j0+jj < Nn) ? g_sdst[(b*NHEADS+h)*Nn + j0+jj] : 0.f;
        }
        // mask tile: read 4 x 32-bit words per thread (int4), store bool bytes
        for (int idx = tid; idx < TI*(TJ/4); idx += 256){
            int r  = idx >> 4;
            int c4 = idx & 15;
            int j  = j0 + c4*4;
            uchar4 mb = make_uchar4(0,0,0,0);
            if (j + 3 < Nn){
                int4 m4 = *(const int4*)(mrow + (size_t)(i0+r)*Nn + j);
                mb.x = (m4.x != 0);
                mb.y = (m4.y != 0);
                mb.z = (m4.z != 0);
                mb.w = (m4.w != 0);
            } else {
                if (j   < Nn) mb.x = (mrow[(size_t)(i0+r)*Nn + j  ] != 0);
                if (j+1 < Nn) mb.y = (mrow[(size_t)(i0+r)*Nn + j+1] != 0);
                if (j+2 < Nn) mb.z = (mrow[(size_t)(i0+r)*Nn + j+2] != 0);
            }
            *(uchar4*)&m_tile[r][c4*4] = mb;
        }
        __syncthreads();

        #pragma unroll
        for (int ps=0; ps<4; ps++){
            int head = ps;
            int iA = w*2, iB = w*2+1;
            float tt0 = t_tile[head][lane];
            float tt1 = t_tile[head][lane+32];
            bool vA0 = m_tile[iA][lane]      != 0;
            bool vA1 = m_tile[iA][lane+32]   != 0;
            bool vB0 = m_tile[iB][lane]      != 0;
            bool vB1 = m_tile[iB][lane+32]   != 0;
            float eA0 = vA0 ? lrelu(sv[ps]   + tt0) : NEG_INF;
            float eA1 = vA1 ? lrelu(sv[ps]   + tt1) : NEG_INF;
            float eB0 = vB0 ? lrelu(sv[ps+4] + tt0) : NEG_INF;
            float eB1 = vB1 ? lrelu(sv[ps+4] + tt1) : NEG_INF;
            float cmA = fmaxf(eA0,eA1), cmB = fmaxf(eB0,eB1);
            #pragma unroll
            for (int off=16; off; off>>=1){
                cmA = fmaxf(cmA, __shfl_xor_sync(0xffffffffu, cmA, off));
                cmB = fmaxf(cmB, __shfl_xor_sync(0xffffffffu, cmB, off));
            }
            float mnA = fmaxf(mv[ps],   cmA);
            float mnB = fmaxf(mv[ps+4], cmB);
            float scA = __expf(mv[ps]   - mnA);
            float scB = __expf(mv[ps+4] - mnB);
            float wA0 = vA0 ? __expf(eA0-mnA) : 0.f;
            float wA1 = vA1 ? __expf(eA1-mnA) : 0.f;
            float wB0 = vB0 ? __expf(eB0-mnB) : 0.f;
            float wB1 = vB1 ? __expf(eB1-mnB) : 0.f;
            float wsA = wA0+wA1, wsB = wB0+wB1;
            #pragma unroll
            for (int off=16; off; off>>=1){
                wsA += __shfl_xor_sync(0xffffffffu, wsA, off);
                wsB += __shfl_xor_sync(0xffffffffu, wsB, off);
            }
            lv[ps]   = lv[ps]  *scA + wsA;  mv[ps]   = mnA;
            lv[ps+4] = lv[ps+4]*scB + wsB;  mv[ps+4] = mnB;
            wb[w][0][lane] = wA0; wb[w][0][lane+32] = wA1;
            wb[w][1][lane] = wB0; wb[w][1][lane+32] = wB1;
            __syncwarp();
            float aA = accv[ps]*scA, aB = accv[ps+4]*scB;
            const float* hp = &h_tile[0][head*DH + lane];
            #pragma unroll
            for (int j4=0;j4<TJ/4;j4++){
                float4 w4A = *(const float4*)&wb[w][0][j4*4];
                float4 w4B = *(const float4*)&wb[w][1][j4*4];
                float h0 = hp[(j4*4+0)*132];
                float h1 = hp[(j4*4+1)*132];
                float h2 = hp[(j4*4+2)*132];
                float h3 = hp[(j4*4+3)*132];
                aA += w4A.x*h0; aB += w4B.x*h0;
                aA += w4A.y*h1; aB += w4B.y*h1;
                aA += w4A.z*h2; aB += w4B.z*h2;
                aA += w4A.w*h3; aB += w4B.w*h3;
            }
            accv[ps]=aA; accv[ps+4]=aB;
            __syncwarp();
        }
    }
    #pragma unroll
    for (int s=0;s<8;s++){
        int rh=w*8+s; int i_l=rh>>2, head=rh&3;
        float outv = accv[s] / lv[s];
        size_t idx = ((size_t)(b*Nn + i0 + i_l))*Dd + head*DH + lane;
        Hout[idx] = outv;
        Cbar[idx] = Cin[idx] - outv;
    }
}

// ---------------- per-horizon deep factor heads ----------------
__global__ void factors_kernel(const float* __restrict__ Cc,
    const float* __restrict__ Cbi, const float* __restrict__ Cbu,
    const float* __restrict__ hW, const float* __restrict__ hb,
    float* __restrict__ out)
{
    int w = threadIdx.x >> 5, lane = threadIdx.x & 31;
    int r = blockIdx.x*4 + w;
    if (r >= Bb*Nn) return;
    float a0=0.f, a1=0.f, a2=0.f;
    #pragma unroll
    for (int it=0; it<12; it++){
        int idx = it*32 + lane;          // 0..383
        const float* src = (idx < 128) ? Cc : (idx < 256 ? Cbi : Cbu);
        int c = idx & 127;
        float v = src[(size_t)r*Dd + c];
        a0 += v*hW[0*DEEP+idx];
        a1 += v*hW[1*DEEP+idx];
        a2 += v*hW[2*DEEP+idx];
    }
    #pragma unroll
    for (int off=16; off; off>>=1){
        a0 += __shfl_xor_sync(0xffffffffu, a0, off);
        a1 += __shfl_xor_sync(0xffffffffu, a1, off);
        a2 += __shfl_xor_sync(0xffffffffu, a2, off);
    }
    if (lane==0){
        out[0*Bb*Nn + r] = lrelu(a0 + hb[0]);
        out[1*Bb*Nn + r] = lrelu(a1 + hb[1]);
        out[2*Bb*Nn + r] = lrelu(a2 + hb[2]);
    }
}

// ---------------- factor attention: U -> A ----------------
__global__ void fa_kernel(const float* __restrict__ feats,
    const float* __restrict__ projW, float* __restrict__ A)
{
    __shared__ float pw[64][65];
    __shared__ float ft[64][64];
    int tid = threadIdx.x;
    int ntile = blockIdx.x & 31;     // 32 tiles of 64 rows
    int hb_   = blockIdx.x >> 5;     // hn*2+b, 0..5
    int hn = hb_ >> 1, b = hb_ & 1;
    int n0 = ntile*64;
    const float* P = projW + (size_t)hn*64*64;
    for (int idx=tid; idx<4096; idx+=256) pw[idx>>6][idx&63] = P[idx];
    for (int idx=tid; idx<4096; idx+=256){
        int r=idx>>6, m=idx&63; int n=n0+r;
        ft[r][m] = (n<Nn) ? feats[((size_t)(b*Nn+n))*Ff+m] : 0.f;
    }
    __syncthreads();
    int w = tid>>5, lane = tid&31;
    for (int rr=0; rr<8; rr++){
        int r = w*8+rr; int n=n0+r;
        if (n>=Nn) continue;
        float u0=0.f,u1=0.f;
        #pragma unroll
        for (int m=0;m<64;m++){
            float f = ft[r][m];
            u0 += f*pw[lane][m];
            u1 += f*pw[lane+32][m];
        }
        u0 = lrelu(u0); u1 = lrelu(u1);
        float mx = fmaxf(u0,u1);
        #pragma unroll
        for (int off=16; off; off>>=1)
            mx = fmaxf(mx, __shfl_xor_sync(0xffffffffu, mx, off));
        float e0 = __expf(u0-mx), e1 = __expf(u1-mx);
        float ss = e0+e1;
        #pragma unroll
        for (int off=16; off; off>>=1)
            ss += __shfl_xor_sync(0xffffffffu, ss, off);
        float inv = 1.f/ss;
        size_t base = ((size_t)hb_*Nn + n)*64;
        A[base+lane]    = e0*inv;
        A[base+lane+32] = e1*inv;
    }
}

// ---------------- a_bar = A.mean(axis=n), deterministic ----------------
__global__ void abar_kernel(const float* __restrict__ A)
{
    __shared__ float red[8][64];
    int tid=threadIdx.x; int k=tid&63, grp=tid>>6;
    const float* base = A + (size_t)blockIdx.x*Nn*64;
    float s=0.f;
    for (int n=grp; n<Nn; n+=8) s += base[(size_t)n*64+k];
    red[grp][k]=s;
    __syncthreads();
    if (grp==0){
        float t=0.f;
        #pragma unroll
        for (int g=0; g<8; g++) t += red[g][k];
        g_abar[blockIdx.x*64+k] = t * (1.f/Nn);
    }
}

// ---------------- recon = feats @ a_bar ----------------
__global__ void recon_kernel(const float* __restrict__ feats, float* __restrict__ out)
{
    int w = threadIdx.x>>5, lane=threadIdx.x&31;
    int ro = blockIdx.x*8 + w;
    if (ro >= HN*Bb*Nn) return;
    int hn = ro / (Bb*Nn);
    int rem = ro % (Bb*Nn);
    int b = rem / Nn, n = rem % Nn;
    const float* f  = feats  + (size_t)(b*Nn+n)*Ff;
    const float* ab = g_abar + (hn*Bb+b)*Ff;
    float p = f[lane]*ab[lane] + f[lane+32]*ab[lane+32];
    #pragma unroll
    for (int off=16; off; off>>=1)
        p += __shfl_xor_sync(0xffffffffu, p, off);
    if (lane==0) out[ro] = p;
}

extern "C" void kernel_launch(void* const* d_in, const int* in_sizes, int n_in,
                              void* d_out, int out_size)
{
    const float* feats = (const float*)d_in[0];
    const int* ind = (const int*)d_in[1];
    const int* uni = (const int*)d_in[2];
    const float* bn_g = (const float*)d_in[3];
    const float* bn_b = (const float*)d_in[4];
    const float* bn_m = (const float*)d_in[5];
    const float* bn_v = (const float*)d_in[6];
    const float* W1   = (const float*)d_in[7];
    const float* b1   = (const float*)d_in[8];
    const float* W2   = (const float*)d_in[9];
    const float* b2   = (const float*)d_in[10];
    const float* giW  = (const float*)d_in[11];
    const float* gias = (const float*)d_in[12];
    const float* giad = (const float*)d_in[13];
    const float* guW  = (const float*)d_in[14];
    const float* guas = (const float*)d_in[15];
    const float* guad = (const float*)d_in[16];
    const float* hW   = (const float*)d_in[17];
    const float* hb   = (const float*)d_in[18];
    const float* pW   = (const float*)d_in[19];

    float* out  = (float*)d_out;
    float* C    = out;                 // (B,N,D)      512000
    float* CBI  = out + 512000;        // (B,N,D)
    float* CBU  = out + 1024000;       // (B,N,D)
    float* HI   = out + 1536000;       // (B,N,D)
    float* HU   = out + 2048000;       // (B,N,D)
    float* FOUT = out + 2560000;       // (Hn,B,N)      12000
    float* ROUT = out + 2572000;       // (Hn,B,N)      12000
    float* AOUT = out + 2584000;       // (Hn,B,N,F)   768000

    encoder_kernel<<<250,128>>>(feats, bn_g, bn_b, bn_m, bn_v, W1, b1, W2, b2, C);

    gat_proj_kernel<<<250,128>>>(C, giW, gias, giad);
    gat_attn_kernel<<<250,256>>>(ind, C, HI, CBI);

    gat_proj_kernel<<<250,128>>>(CBI, guW, guas, guad);
    gat_attn_kernel<<<250,256>>>(uni, CBI, HU, CBU);

    factors_kernel<<<1000,128>>>(C, CBI, CBU, hW, hb, FOUT);

    fa_kernel<<<192,256>>>(feats, pW, AOUT);
    abar_kernel<<<6,512>>>(AOUT);
    recon_kernel<<<1500,256>>>(feats, ROUT);
}

// round 4
// speedup vs baseline: 1.4084x; 1.4084x over previous
#include <cuda_runtime.h>

#define Bb 2
#define Nn 2000
#define Ff 64
#define Dd 128
#define NHEADS 4
#define DH 32
#define HN 3
#define DEEP 384
#define SLOPE 0.1f
#define NEG_INF -1e30f
#define TJ 64
#define TI 16
#define LOG2E 1.44269504f

__device__ float g_hbuf[Bb*Nn*Dd];
__device__ float g_ssrc[Bb*NHEADS*Nn];
__device__ float g_sdst[Bb*NHEADS*Nn];
__device__ float g_tmax[Bb*NHEADS];
__device__ float g_abar[HN*Bb*Ff];

__device__ __forceinline__ float lrelu(float x){ return fmaxf(x, SLOPE*x); }

__device__ __forceinline__ unsigned long long pk2(float lo, float hi){
    unsigned long long r;
    asm("mov.b64 %0, {%1,%2};" : "=l"(r) : "f"(lo), "f"(hi));
    return r;
}
__device__ __forceinline__ void upk2(unsigned long long v, float& lo, float& hi){
    asm("mov.b64 {%0,%1}, %2;" : "=f"(lo), "=f"(hi) : "l"(v));
}
__device__ __forceinline__ void ffma2(unsigned long long& acc,
                                      unsigned long long a, unsigned long long b){
    asm("fma.rn.f32x2 %0, %1, %2, %0;" : "+l"(acc) : "l"(a), "l"(b));
}

// ---------------- BN + encoder MLP: features -> C ----------------
__global__ __launch_bounds__(256) void encoder_kernel(const float* __restrict__ feats,
    const float* __restrict__ gamma, const float* __restrict__ beta,
    const float* __restrict__ mean, const float* __restrict__ var,
    const float* __restrict__ W1, const float* __restrict__ b1,
    const float* __restrict__ W2, const float* __restrict__ b2,
    float* __restrict__ C)
{
    __shared__ float xn[16][Ff];
    __shared__ float hid[16][Dd];
    int tid = threadIdx.x;
    int col = tid & 127, grp = tid >> 7;
    int row0 = blockIdx.x * 16;
    for (int idx = tid; idx < 16*Ff; idx += 256) {
        int r = idx >> 6, f = idx & 63;
        float v = feats[(size_t)(row0+r)*Ff + f];
        xn[r][f] = (v - mean[f]) * rsqrtf(var[f] + 1e-5f) * gamma[f] + beta[f];
    }
    __syncthreads();
    float acc[8];
    float bb = b1[col];
    #pragma unroll
    for (int r=0;r<8;r++) acc[r] = bb;
    #pragma unroll 4
    for (int f=0; f<Ff; f++){
        float w = W1[f*Dd + col];
        #pragma unroll
        for (int r=0;r<8;r++) acc[r] += xn[grp*8+r][f]*w;
    }
    #pragma unroll
    for (int r=0;r<8;r++) hid[grp*8+r][col] = fmaxf(acc[r], 0.f);
    __syncthreads();
    bb = b2[col];
    #pragma unroll
    for (int r=0;r<8;r++) acc[r] = bb;
    #pragma unroll 4
    for (int k=0;k<Dd;k++){
        float w = W2[k*Dd + col];
        #pragma unroll
        for (int r=0;r<8;r++) acc[r] += hid[grp*8+r][k]*w;
    }
    #pragma unroll
    for (int r=0;r<8;r++) C[(size_t)(row0+grp*8+r)*Dd + col] = acc[r];
}

// ---------------- GAT projection: h = X@W, s_src, s_dst ----------------
__global__ __launch_bounds__(256) void gat_proj_kernel(const float* __restrict__ X,
    const float* __restrict__ W, const float* __restrict__ a_src,
    const float* __restrict__ a_dst)
{
    __shared__ float xs[16][Dd];
    int tid = threadIdx.x;
    int col = tid & 127, grp = tid >> 7;
    int row0 = blockIdx.x * 16;
    for (int idx = tid; idx < 16*32; idx += 256){
        int r = idx >> 5, c4 = idx & 31;
        *(float4*)&xs[r][c4*4] = *(const float4*)(X + (size_t)(row0+r)*Dd + c4*4);
    }
    __syncthreads();
    float acc[8];
    #pragma unroll
    for (int r=0;r<8;r++) acc[r]=0.f;
    #pragma unroll 4
    for (int k=0;k<Dd;k++){
        float w = W[k*Dd + col];
        #pragma unroll
        for (int r=0;r<8;r++) acc[r] += xs[grp*8+r][k]*w;
    }
    int head = col >> 5, lane = col & 31;
    float av = a_src[head*DH + lane];
    float bv = a_dst[head*DH + lane];
    #pragma unroll
    for (int r=0;r<8;r++){
        int g = row0 + grp*8 + r;
        g_hbuf[(size_t)g*Dd + col] = acc[r];
        float p = acc[r]*av, q = acc[r]*bv;
        #pragma unroll
        for (int off=16; off; off>>=1){
            p += __shfl_xor_sync(0xffffffffu, p, off);
            q += __shfl_xor_sync(0xffffffffu, q, off);
        }
        if (lane == 0){
            int b = g / Nn, n = g % Nn;
            g_ssrc[(b*NHEADS+head)*Nn + n] = p;
            g_sdst[(b*NHEADS+head)*Nn + n] = q;
        }
    }
}

// ---------------- per-(b,head) max of s_dst ----------------
__global__ void tmax_kernel()
{
    __shared__ float red[256];
    const float* t = g_sdst + blockIdx.x * Nn;
    float m = NEG_INF;
    for (int n = threadIdx.x; n < Nn; n += 256) m = fmaxf(m, t[n]);
    red[threadIdx.x] = m;
    __syncthreads();
    #pragma unroll
    for (int s=128; s; s>>=1){
        if (threadIdx.x < s) red[threadIdx.x] = fmaxf(red[threadIdx.x], red[threadIdx.x+s]);
        __syncthreads();
    }
    if (threadIdx.x == 0) g_tmax[blockIdx.x] = red[0];
}

// ---------------- GAT attention: fixed-shift softmax + f32x2 aggregation ----
// 256 threads, 8 warps. Warp w: head = w&3, row-group rg = w>>2 (8 rows each).
// Softmax shift m_i = lrelu(s_i + max_j t_j) is an upper bound on every e_ij
// (lrelu monotone), so no online rescaling is needed; weights <= 1.
__global__ __launch_bounds__(256) void gat_attn_kernel(const int* __restrict__ mask,
    const float* __restrict__ Cin, float* __restrict__ Hout, float* __restrict__ Cbar)
{
    __shared__ float h_tile[TJ][132];
    __shared__ float t_tile[NHEADS][TJ];
    __shared__ unsigned char m_tile[TI][TJ];
    __shared__ float2 wb[8][4][TJ];

    int tid = threadIdx.x;
    int w = tid >> 5, lane = tid & 31;
    int h = w & 3, rg = w >> 2;
    int b  = blockIdx.x / (Nn/TI);
    int i0 = (blockIdx.x % (Nn/TI)) * TI;
    int irbase = i0 + rg*8;

    float sv[8], m2[8], lvp[8];
    unsigned long long acc2[4];
    float tmx = g_tmax[b*NHEADS + h];
    #pragma unroll
    for (int r=0;r<8;r++){
        float s = g_ssrc[(b*NHEADS+h)*Nn + irbase + r];
        sv[r] = s;
        m2[r] = lrelu(s + tmx) * LOG2E;
        lvp[r] = 0.f;
    }
    #pragma unroll
    for (int p=0;p<4;p++) acc2[p] = 0ull;

    const float* hb = g_hbuf + (size_t)b*Nn*Dd;
    const int* mrow = mask + (size_t)b*Nn*Nn + (size_t)i0*Nn;

    for (int j0 = 0; j0 < Nn; j0 += TJ){
        __syncthreads();
        // h tile (zero-fill past N)
        for (int idx = tid; idx < TJ*(Dd/4); idx += 256){
            int jj = idx >> 5;
            int c4 = idx & 31;
            float4 v = make_float4(0.f,0.f,0.f,0.f);
            if (j0+jj < Nn) v = *(const float4*)(hb + (size_t)(j0+jj)*Dd + c4*4);
            *(float4*)&h_tile[jj][c4*4] = v;
        }
        // s_dst tile
        {
            int hh = tid / TJ, jj = tid % TJ;
            t_tile[hh][jj] = (j0+jj < Nn) ? g_sdst[(b*NHEADS+hh)*Nn + j0+jj] : 0.f;
        }
        // mask tile: 16 rows x 64 j, int32 words -> bool bytes
        {
            int r  = tid >> 4;
            int c4 = tid & 15;
            int j  = j0 + c4*4;
            uchar4 mb = make_uchar4(0,0,0,0);
            if (j + 3 < Nn){
                int4 m4 = *(const int4*)(mrow + (size_t)r*Nn + j);
                mb.x = (m4.x != 0); mb.y = (m4.y != 0);
                mb.z = (m4.z != 0); mb.w = (m4.w != 0);
            } else {
                if (j   < Nn) mb.x = (mrow[(size_t)r*Nn + j  ] != 0);
                if (j+1 < Nn) mb.y = (mrow[(size_t)r*Nn + j+1] != 0);
                if (j+2 < Nn) mb.z = (mrow[(size_t)r*Nn + j+2] != 0);
            }
            *(uchar4*)&m_tile[r][c4*4] = mb;
        }
        __syncthreads();

        // ---- weights: lanes over j (j=lane, j=lane+32), rows in pairs ----
        float t0 = t_tile[h][lane];
        float t1 = t_tile[h][lane+32];
        #pragma unroll
        for (int p=0;p<4;p++){
            int r0 = 2*p, r1 = 2*p+1;
            unsigned char ma0 = m_tile[rg*8+r0][lane];
            unsigned char ma1 = m_tile[rg*8+r0][lane+32];
            unsigned char mb0 = m_tile[rg*8+r1][lane];
            unsigned char mb1 = m_tile[rg*8+r1][lane+32];
            float l00 = lrelu(sv[r0] + t0);
            float l01 = lrelu(sv[r0] + t1);
            float l10 = lrelu(sv[r1] + t0);
            float l11 = lrelu(sv[r1] + t1);
            float w00 = ma0 ? exp2f(fmaf(l00, LOG2E, -m2[r0])) : 0.f;
            float w01 = ma1 ? exp2f(fmaf(l01, LOG2E, -m2[r0])) : 0.f;
            float w10 = mb0 ? exp2f(fmaf(l10, LOG2E, -m2[r1])) : 0.f;
            float w11 = mb1 ? exp2f(fmaf(l11, LOG2E, -m2[r1])) : 0.f;
            lvp[r0] += w00 + w01;
            lvp[r1] += w10 + w11;
            wb[w][p][lane]    = make_float2(w00, w10);
            wb[w][p][lane+32] = make_float2(w01, w11);
        }
        __syncwarp();

        // ---- aggregation: lanes over d, packed row-pairs via fma.rn.f32x2 ----
        const float* hp = &h_tile[0][h*DH + lane];
        #pragma unroll 4
        for (int j4=0; j4<TJ/4; j4++){
            float hv0 = hp[(j4*4+0)*132];
            float hv1 = hp[(j4*4+1)*132];
            float hv2 = hp[(j4*4+2)*132];
            float hv3 = hp[(j4*4+3)*132];
            unsigned long long H0 = pk2(hv0,hv0);
            unsigned long long H1 = pk2(hv1,hv1);
            unsigned long long H2 = pk2(hv2,hv2);
            unsigned long long H3 = pk2(hv3,hv3);
            #pragma unroll
            for (int p=0;p<4;p++){
                ulonglong2 wA = *(const ulonglong2*)&wb[w][p][j4*4];
                ulonglong2 wB = *(const ulonglong2*)&wb[w][p][j4*4+2];
                ffma2(acc2[p], wA.x, H0);
                ffma2(acc2[p], wA.y, H1);
                ffma2(acc2[p], wB.x, H2);
                ffma2(acc2[p], wB.y, H3);
            }
        }
        __syncwarp();
    }

    // reduce lv over lanes (j-domain), then normalize + write
    #pragma unroll
    for (int r=0;r<8;r++){
        #pragma unroll
        for (int off=16; off; off>>=1)
            lvp[r] += __shfl_xor_sync(0xffffffffu, lvp[r], off);
    }
    #pragma unroll
    for (int p=0;p<4;p++){
        float a0, a1;
        upk2(acc2[p], a0, a1);
        float o0 = __fdividef(a0, lvp[2*p]);
        float o1 = __fdividef(a1, lvp[2*p+1]);
        size_t x0 = ((size_t)(b*Nn + irbase + 2*p))*Dd + h*DH + lane;
        size_t x1 = x0 + Dd;
        Hout[x0] = o0; Cbar[x0] = Cin[x0] - o0;
        Hout[x1] = o1; Cbar[x1] = Cin[x1] - o1;
    }
}

// ---------------- per-horizon deep factor heads ----------------
__global__ void factors_kernel(const float* __restrict__ Cc,
    const float* __restrict__ Cbi, const float* __restrict__ Cbu,
    const float* __restrict__ hW, const float* __restrict__ hb,
    float* __restrict__ out)
{
    int w = threadIdx.x >> 5, lane = threadIdx.x & 31;
    int r = blockIdx.x*4 + w;
    if (r >= Bb*Nn) return;
    float a0=0.f, a1=0.f, a2=0.f;
    #pragma unroll
    for (int it=0; it<12; it++){
        int idx = it*32 + lane;
        const float* src = (idx < 128) ? Cc : (idx < 256 ? Cbi : Cbu);
        int c = idx & 127;
        float v = src[(size_t)r*Dd + c];
        a0 += v*hW[0*DEEP+idx];
        a1 += v*hW[1*DEEP+idx];
        a2 += v*hW[2*DEEP+idx];
    }
    #pragma unroll
    for (int off=16; off; off>>=1){
        a0 += __shfl_xor_sync(0xffffffffu, a0, off);
        a1 += __shfl_xor_sync(0xffffffffu, a1, off);
        a2 += __shfl_xor_sync(0xffffffffu, a2, off);
    }
    if (lane==0){
        out[0*Bb*Nn + r] = lrelu(a0 + hb[0]);
        out[1*Bb*Nn + r] = lrelu(a1 + hb[1]);
        out[2*Bb*Nn + r] = lrelu(a2 + hb[2]);
    }
}

// ---------------- factor attention: U -> A ----------------
__global__ void fa_kernel(const float* __restrict__ feats,
    const float* __restrict__ projW, float* __restrict__ A)
{
    __shared__ float pw[64][65];
    __shared__ float ft[64][64];
    int tid = threadIdx.x;
    int ntile = blockIdx.x & 31;
    int hb_   = blockIdx.x >> 5;
    int hn = hb_ >> 1, b = hb_ & 1;
    int n0 = ntile*64;
    const float* P = projW + (size_t)hn*64*64;
    for (int idx=tid; idx<4096; idx+=256) pw[idx>>6][idx&63] = P[idx];
    for (int idx=tid; idx<4096; idx+=256){
        int r=idx>>6, m=idx&63; int n=n0+r;
        ft[r][m] = (n<Nn) ? feats[((size_t)(b*Nn+n))*Ff+m] : 0.f;
    }
    __syncthreads();
    int w = tid>>5, lane = tid&31;
    for (int rr=0; rr<8; rr++){
        int r = w*8+rr; int n=n0+r;
        if (n>=Nn) continue;
        float u0=0.f,u1=0.f;
        #pragma unroll
        for (int m=0;m<64;m++){
            float f = ft[r][m];
            u0 += f*pw[lane][m];
            u1 += f*pw[lane+32][m];
        }
        u0 = lrelu(u0); u1 = lrelu(u1);
        float mx = fmaxf(u0,u1);
        #pragma unroll
        for (int off=16; off; off>>=1)
            mx = fmaxf(mx, __shfl_xor_sync(0xffffffffu, mx, off));
        float e0 = __expf(u0-mx), e1 = __expf(u1-mx);
        float ss = e0+e1;
        #pragma unroll
        for (int off=16; off; off>>=1)
            ss += __shfl_xor_sync(0xffffffffu, ss, off);
        float inv = 1.f/ss;
        size_t base = ((size_t)hb_*Nn + n)*64;
        A[base+lane]    = e0*inv;
        A[base+lane+32] = e1*inv;
    }
}

// ---------------- a_bar = A.mean(axis=n) ----------------
__global__ void abar_kernel(const float* __restrict__ A)
{
    __shared__ float red[8][64];
    int tid=threadIdx.x; int k=tid&63, grp=tid>>6;
    const float* base = A + (size_t)blockIdx.x*Nn*64;
    float s=0.f;
    for (int n=grp; n<Nn; n+=8) s += base[(size_t)n*64+k];
    red[grp][k]=s;
    __syncthreads();
    if (grp==0){
        float t=0.f;
        #pragma unroll
        for (int g=0; g<8; g++) t += red[g][k];
        g_abar[blockIdx.x*64+k] = t * (1.f/Nn);
    }
}

// ---------------- recon = feats @ a_bar ----------------
__global__ void recon_kernel(const float* __restrict__ feats, float* __restrict__ out)
{
    int w = threadIdx.x>>5, lane=threadIdx.x&31;
    int ro = blockIdx.x*8 + w;
    if (ro >= HN*Bb*Nn) return;
    int hn = ro / (Bb*Nn);
    int rem = ro % (Bb*Nn);
    int b = rem / Nn, n = rem % Nn;
    const float* f  = feats  + (size_t)(b*Nn+n)*Ff;
    const float* ab = g_abar + (hn*Bb+b)*Ff;
    float p = f[lane]*ab[lane] + f[lane+32]*ab[lane+32];
    #pragma unroll
    for (int off=16; off; off>>=1)
        p += __shfl_xor_sync(0xffffffffu, p, off);
    if (lane==0) out[ro] = p;
}

extern "C" void kernel_launch(void* const* d_in, const int* in_sizes, int n_in,
                              void* d_out, int out_size)
{
    const float* feats = (const float*)d_in[0];
    const int* ind = (const int*)d_in[1];
    const int* uni = (const int*)d_in[2];
    const float* bn_g = (const float*)d_in[3];
    const float* bn_b = (const float*)d_in[4];
    const float* bn_m = (const float*)d_in[5];
    const float* bn_v = (const float*)d_in[6];
    const float* W1   = (const float*)d_in[7];
    const float* b1   = (const float*)d_in[8];
    const float* W2   = (const float*)d_in[9];
    const float* b2   = (const float*)d_in[10];
    const float* giW  = (const float*)d_in[11];
    const float* gias = (const float*)d_in[12];
    const float* giad = (const float*)d_in[13];
    const float* guW  = (const float*)d_in[14];
    const float* guas = (const float*)d_in[15];
    const float* guad = (const float*)d_in[16];
    const float* hW   = (const float*)d_in[17];
    const float* hb   = (const float*)d_in[18];
    const float* pW   = (const float*)d_in[19];

    float* out  = (float*)d_out;
    float* C    = out;                 // (B,N,D)
    float* CBI  = out + 512000;
    float* CBU  = out + 1024000;
    float* HI   = out + 1536000;
    float* HU   = out + 2048000;
    float* FOUT = out + 2560000;       // (Hn,B,N)
    float* ROUT = out + 2572000;       // (Hn,B,N)
    float* AOUT = out + 2584000;       // (Hn,B,N,F)

    encoder_kernel<<<250,256>>>(feats, bn_g, bn_b, bn_m, bn_v, W1, b1, W2, b2, C);

    gat_proj_kernel<<<250,256>>>(C, giW, gias, giad);
    tmax_kernel<<<8,256>>>();
    gat_attn_kernel<<<250,256>>>(ind, C, HI, CBI);

    gat_proj_kernel<<<250,256>>>(CBI, guW, guas, guad);
    tmax_kernel<<<8,256>>>();
    gat_attn_kernel<<<250,256>>>(uni, CBI, HU, CBU);

    factors_kernel<<<1000,128>>>(C, CBI, CBU, hW, hb, FOUT);

    fa_kernel<<<192,256>>>(feats, pW, AOUT);
    abar_kernel<<<6,512>>>(AOUT);
    recon_kernel<<<1500,256>>>(feats, ROUT);
}